// round 11
// baseline (speedup 1.0000x reference)
#include <cuda_runtime.h>
#include <cuda_bf16.h>
#include <cstdint>

// ---------------- problem constants ----------------
#define SS    1024
#define INW   32
#define HH    128
#define NTHR  256          // 8 warps; warp w owns all 4 gate types of units w*16..w*16+15
#define NBLK  128          // 4 batch rows per CTA
#define KTOT  160          // 128 h + 32 x
#define NKT   10           // k16 tiles
#define NKR   8            // k16 tiles with W_hi in registers
#define BST   168          // B staging stride in bf16 (conflict-free)
#define BTERM (8 * BST * 2)        // 2688 B per term (hi or lo)
#define BBUF  (2 * BTERM)          // one ping-pong buffer (hi+lo)

#define OFF_ALO    0
#define ALO_BYTES  (512 * KTOT * 2)            // 163840: W_lo fragments
#define OFF_AHI    ALO_BYTES                    // W_hi fragments for kt = 8,9
#define AHI_BYTES  (8 * 4 * 2 * 32 * 16)       // 32768
#define OFF_B      (OFF_AHI + AHI_BYTES)       // 196608: 2 ping-pong buffers
#define OFF_LRED   (OFF_B + 2 * BBUF)          // 218112
#define SMEM_BYTES (OFF_LRED + 256)            // 218368 < cap

// ---------------- helpers ----------------
__device__ __forceinline__ unsigned short bf16_bits(float v) {
    __nv_bfloat16 b = __float2bfloat16(v);
    return *reinterpret_cast<unsigned short*>(&b);
}
__device__ __forceinline__ float bf16_val(unsigned short s) {
    __nv_bfloat16 b = *reinterpret_cast<__nv_bfloat16*>(&s);
    return __bfloat162float(b);
}
__device__ __forceinline__ void split_bf16(float w, unsigned short& hi, unsigned short& lo) {
    hi = bf16_bits(w);
    lo = bf16_bits(w - bf16_val(hi));
}
__device__ __forceinline__ uint32_t pack2(unsigned short a16, unsigned short b16) {
    return (uint32_t)a16 | ((uint32_t)b16 << 16);
}
__device__ __forceinline__ void mma_bf16(float& d0, float& d1, float& d2, float& d3,
                                         uint32_t a0, uint32_t a1, uint32_t a2, uint32_t a3,
                                         uint32_t b0, uint32_t b1) {
    asm volatile(
        "mma.sync.aligned.m16n8k16.row.col.f32.bf16.bf16.f32 "
        "{%0,%1,%2,%3}, {%4,%5,%6,%7}, {%8,%9}, {%0,%1,%2,%3};"
        : "+f"(d0), "+f"(d1), "+f"(d2), "+f"(d3)
        : "r"(a0), "r"(a1), "r"(a2), "r"(a3), "r"(b0), "r"(b1));
}
__device__ __forceinline__ float sigmoid_f(float v) {
    return __fdividef(1.0f, 1.0f + __expf(-v));
}
__device__ __forceinline__ float tanh_f(float v) {
    return 1.0f - __fdividef(2.0f, __expf(2.0f * v) + 1.0f);
}

__global__ void __launch_bounds__(NTHR, 1)
lstm_mma_kernel(const float* __restrict__ x,     // [B,S,IN]
                const float* __restrict__ Wih,   // [4H,IN]
                const float* __restrict__ Whh,   // [4H,H]
                const float* __restrict__ bih,   // [4H]
                const float* __restrict__ bhh,   // [4H]
                const float* __restrict__ Wlin,  // [1, S*H]
                const float* __restrict__ blin,  // [1]
                float* __restrict__ out)         // [B,1]
{
    extern __shared__ char smc[];
    float* smf = reinterpret_cast<float*>(smc);
    const int tid  = threadIdx.x;
    const int wid  = tid >> 5;
    const int lane = tid & 31;
    const int b0   = blockIdx.x * 4;

    // ---------------- prologue ----------------
    for (int i = tid; i < (2 * BBUF) / 4; i += NTHR)
        reinterpret_cast<uint32_t*>(smc + OFF_B)[i] = 0;

    // W fragments. Warp w, m-tile mt = gate type mt of units w*16..w*16+15:
    //   g = mt*128 + wid*16 + r (+8 for rg&1), k per rg&2.
    // hi kt 0..7 -> registers; hi kt 8,9 -> smem AHI; lo all kt -> smem ALO.
    uint32_t wa[4][NKR][4];
    {
        const int r  = lane >> 2;
        const int kc = (lane & 3) * 2;
        #pragma unroll
        for (int mt = 0; mt < 4; mt++) {
            #pragma unroll
            for (int kt = 0; kt < NKT; kt++) {
                uint32_t hi4[4], lo4[4];
                #pragma unroll
                for (int rg = 0; rg < 4; rg++) {
                    int g = mt * 128 + wid * 16 + r + ((rg & 1) ? 8 : 0);
                    int k = kt * 16 + kc + ((rg & 2) ? 8 : 0);
                    float2 w2;
                    if (k < HH) w2 = *reinterpret_cast<const float2*>(Whh + (size_t)g * HH + k);
                    else        w2 = *reinterpret_cast<const float2*>(Wih + (size_t)g * INW + (k - HH));
                    unsigned short h0, l0, h1, l1;
                    split_bf16(w2.x, h0, l0);
                    split_bf16(w2.y, h1, l1);
                    hi4[rg] = pack2(h0, h1);
                    lo4[rg] = pack2(l0, l1);
                }
                *reinterpret_cast<uint4*>(smc + OFF_ALO +
                    (size_t)((((wid * 4 + mt) * NKT + kt) * 32 + lane) * 16))
                    = make_uint4(lo4[0], lo4[1], lo4[2], lo4[3]);
                if (kt < NKR) {
                    wa[mt][kt][0] = hi4[0]; wa[mt][kt][1] = hi4[1];
                    wa[mt][kt][2] = hi4[2]; wa[mt][kt][3] = hi4[3];
                } else {
                    *reinterpret_cast<uint4*>(smc + OFF_AHI +
                        (size_t)((((wid * 4 + mt) * 2 + (kt - NKR)) * 32 + lane) * 16))
                        = make_uint4(hi4[0], hi4[1], hi4[2], hi4[3]);
                }
            }
        }
    }

    // ew roles: active lanes have (lane & 2) == 0.
    //   u = lane>>2 (0..7): units ju = wid*16+u and jv = ju+8
    //   bsel = lane&1: batch rows n0 = 2*bsel, n1 = n0+1
    const bool ew_act = (lane & 2) == 0;
    const int  u    = lane >> 2;
    const int  bsel = lane & 1;
    const int  n0   = 2 * bsel;
    const int  ju   = wid * 16 + u;
    const int  jv   = ju + 8;
    float bU[4], bV[4];
    #pragma unroll
    for (int mt = 0; mt < 4; mt++) {
        bU[mt] = bih[mt * 128 + ju] + bhh[mt * 128 + ju];
        bV[mt] = bih[mt * 128 + jv] + bhh[mt * 128 + jv];
    }
    // c-states: [unit(u/v)][row(n0/n0+1)]
    float cU0 = 0.f, cU1 = 0.f, cV0 = 0.f, cV1 = 0.f;
    float linU0 = 0.f, linU1 = 0.f, linV0 = 0.f, linV1 = 0.f;

    __syncthreads();                       // staging zero complete
    if (tid < 64) {
        int row = tid >> 4, i0 = (tid & 15) * 2;
        float2 xv = *reinterpret_cast<const float2*>(
            x + ((size_t)(b0 + row) * SS + 0) * INW + i0);
        unsigned short h0, l0, h1, l1;
        split_bf16(xv.x, h0, l0);
        split_bf16(xv.y, h1, l1);
        char* p = smc + OFF_B + (size_t)(row * BST + HH + i0) * 2;   // buf 0
        *reinterpret_cast<uint32_t*>(p)         = pack2(h0, h1);
        *reinterpret_cast<uint32_t*>(p + BTERM) = pack2(l0, l1);
    }
    __syncthreads();

    const int bn = lane >> 2;
    const int bk = (lane & 3) * 2;

    // ---------------- main recurrence ----------------
    #pragma unroll 1
    for (int t = 0; t < SS; t++) {
        // early independent global loads
        float wlU = 0.f, wlV = 0.f;
        if (ew_act) {
            wlU = __ldg(Wlin + (size_t)t * HH + ju);
            wlV = __ldg(Wlin + (size_t)t * HH + jv);
        }
        float2 xv = make_float2(0.0f, 0.0f);
        if (tid < 64) {
            int row = tid >> 4, i0 = (tid & 15) * 2;
            int tn = (t + 1 < SS) ? (t + 1) : (SS - 1);
            xv = *reinterpret_cast<const float2*>(
                x + ((size_t)(b0 + row) * SS + tn) * INW + i0);
        }

        const char* bbase = smc + OFF_B + (size_t)(t & 1) * BBUF;

        // === MMA phase: term-major inner order ===
        float d0[4], d1[4], d2[4], d3[4];
        #pragma unroll
        for (int mt = 0; mt < 4; mt++) { d0[mt] = 0.f; d1[mt] = 0.f; d2[mt] = 0.f; d3[mt] = 0.f; }

        #pragma unroll
        for (int kt = 0; kt < NKT; kt++) {
            const char* bb = bbase + (size_t)((bn * BST + kt * 16 + bk) * 2);
            uint32_t bh0 = *reinterpret_cast<const uint32_t*>(bb);
            uint32_t bh1 = *reinterpret_cast<const uint32_t*>(bb + 16);
            uint32_t bl0 = *reinterpret_cast<const uint32_t*>(bb + BTERM);
            uint32_t bl1 = *reinterpret_cast<const uint32_t*>(bb + BTERM + 16);

            uint32_t ah[4][4];
            if (kt < NKR) {
                #pragma unroll
                for (int mt = 0; mt < 4; mt++) {
                    ah[mt][0] = wa[mt][kt][0]; ah[mt][1] = wa[mt][kt][1];
                    ah[mt][2] = wa[mt][kt][2]; ah[mt][3] = wa[mt][kt][3];
                }
            } else {
                #pragma unroll
                for (int mt = 0; mt < 4; mt++) {
                    const uint4 v = *reinterpret_cast<const uint4*>(smc + OFF_AHI +
                        (size_t)((((wid * 4 + mt) * 2 + (kt - NKR)) * 32 + lane) * 16));
                    ah[mt][0] = v.x; ah[mt][1] = v.y; ah[mt][2] = v.z; ah[mt][3] = v.w;
                }
            }
            uint4 alo[4];
            #pragma unroll
            for (int mt = 0; mt < 4; mt++)
                alo[mt] = *reinterpret_cast<const uint4*>(smc + OFF_ALO +
                    (size_t)((((wid * 4 + mt) * NKT + kt) * 32 + lane) * 16));

            #pragma unroll
            for (int mt = 0; mt < 4; mt++)
                mma_bf16(d0[mt], d1[mt], d2[mt], d3[mt],
                         ah[mt][0], ah[mt][1], ah[mt][2], ah[mt][3], bh0, bh1);
            #pragma unroll
            for (int mt = 0; mt < 4; mt++)
                mma_bf16(d0[mt], d1[mt], d2[mt], d3[mt],
                         ah[mt][0], ah[mt][1], ah[mt][2], ah[mt][3], bl0, bl1);
            #pragma unroll
            for (int mt = 0; mt < 4; mt++)
                mma_bf16(d0[mt], d1[mt], d2[mt], d3[mt],
                         alo[mt].x, alo[mt].y, alo[mt].z, alo[mt].w, bh0, bh1);
        }

        // === in-register elementwise ===
        // Lane holds: d0[mt] = (unit ju, row n0), d1[mt] = (ju, n0+1),
        //             d2[mt] = (jv, n0),          d3[mt] = (jv, n0+1).
        char* nbase = smc + OFF_B + (size_t)((t + 1) & 1) * BBUF;
        if (ew_act) {
            // cell (ju, n0)
            {
                float iv = sigmoid_f(d0[0] + bU[0]);
                float fv = sigmoid_f(d0[1] + bU[1]);
                float gv = tanh_f(d0[2] + bU[2]);
                float ov = sigmoid_f(d0[3] + bU[3]);
                cU0 = fmaf(fv, cU0, iv * gv);
                float hv = ov * tanh_f(cU0);
                linU0 = fmaf(hv, wlU, linU0);
                unsigned short h16, l16; split_bf16(hv, h16, l16);
                char* p = nbase + (size_t)(n0 * BST + ju) * 2;
                *reinterpret_cast<unsigned short*>(p)         = h16;
                *reinterpret_cast<unsigned short*>(p + BTERM) = l16;
            }
            // cell (ju, n0+1)
            {
                float iv = sigmoid_f(d1[0] + bU[0]);
                float fv = sigmoid_f(d1[1] + bU[1]);
                float gv = tanh_f(d1[2] + bU[2]);
                float ov = sigmoid_f(d1[3] + bU[3]);
                cU1 = fmaf(fv, cU1, iv * gv);
                float hv = ov * tanh_f(cU1);
                linU1 = fmaf(hv, wlU, linU1);
                unsigned short h16, l16; split_bf16(hv, h16, l16);
                char* p = nbase + (size_t)((n0 + 1) * BST + ju) * 2;
                *reinterpret_cast<unsigned short*>(p)         = h16;
                *reinterpret_cast<unsigned short*>(p + BTERM) = l16;
            }
            // cell (jv, n0)
            {
                float iv = sigmoid_f(d2[0] + bV[0]);
                float fv = sigmoid_f(d2[1] + bV[1]);
                float gv = tanh_f(d2[2] + bV[2]);
                float ov = sigmoid_f(d2[3] + bV[3]);
                cV0 = fmaf(fv, cV0, iv * gv);
                float hv = ov * tanh_f(cV0);
                linV0 = fmaf(hv, wlV, linV0);
                unsigned short h16, l16; split_bf16(hv, h16, l16);
                char* p = nbase + (size_t)(n0 * BST + jv) * 2;
                *reinterpret_cast<unsigned short*>(p)         = h16;
                *reinterpret_cast<unsigned short*>(p + BTERM) = l16;
            }
            // cell (jv, n0+1)
            {
                float iv = sigmoid_f(d3[0] + bV[0]);
                float fv = sigmoid_f(d3[1] + bV[1]);
                float gv = tanh_f(d3[2] + bV[2]);
                float ov = sigmoid_f(d3[3] + bV[3]);
                cV1 = fmaf(fv, cV1, iv * gv);
                float hv = ov * tanh_f(cV1);
                linV1 = fmaf(hv, wlV, linV1);
                unsigned short h16, l16; split_bf16(hv, h16, l16);
                char* p = nbase + (size_t)((n0 + 1) * BST + jv) * 2;
                *reinterpret_cast<unsigned short*>(p)         = h16;
                *reinterpret_cast<unsigned short*>(p + BTERM) = l16;
            }
        }
        // x(t+1) into next buffer
        if (tid < 64) {
            int row = tid >> 4, i0 = (tid & 15) * 2;
            unsigned short h0, l0, h1, l1;
            split_bf16(xv.x, h0, l0);
            split_bf16(xv.y, h1, l1);
            char* p = nbase + (size_t)(row * BST + HH + i0) * 2;
            *reinterpret_cast<uint32_t*>(p)         = pack2(h0, h1);
            *reinterpret_cast<uint32_t*>(p + BTERM) = pack2(l0, l1);
        }
        __syncthreads();                  // single barrier per step
    }

    // ---------------- epilogue ----------------
    // Per active lane: linU0+linV0 = partial for row n0; linU1+linV1 for n0+1.
    float l0s = linU0 + linV0;
    float l1s = linU1 + linV1;
    #pragma unroll
    for (int off = 4; off <= 16; off <<= 1) {
        l0s += __shfl_xor_sync(0xffffffffu, l0s, off);   // sum over u (bits 2..4)
        l1s += __shfl_xor_sync(0xffffffffu, l1s, off);
    }
    if (lane < 2) {                       // lane == bsel, u == 0
        smf[(OFF_LRED >> 2) + wid * 4 + 2 * lane]     = l0s;   // row 2*bsel
        smf[(OFF_LRED >> 2) + wid * 4 + 2 * lane + 1] = l1s;   // row 2*bsel+1
    }
    __syncthreads();
    if (tid < 4) {
        float s = blin[0];
        #pragma unroll
        for (int w = 0; w < 8; w++) s += smf[(OFF_LRED >> 2) + w * 4 + tid];
        out[b0 + tid] = s;
    }
}

extern "C" void kernel_launch(void* const* d_in, const int* in_sizes, int n_in,
                              void* d_out, int out_size)
{
    const float* x    = (const float*)d_in[0];
    const float* Wih  = (const float*)d_in[1];
    const float* Whh  = (const float*)d_in[2];
    const float* bih  = (const float*)d_in[3];
    const float* bhh  = (const float*)d_in[4];
    const float* Wlin = (const float*)d_in[5];
    const float* blin = (const float*)d_in[6];
    float* out = (float*)d_out;

    cudaFuncSetAttribute(lstm_mma_kernel,
                         cudaFuncAttributeMaxDynamicSharedMemorySize, SMEM_BYTES);
    lstm_mma_kernel<<<NBLK, NTHR, SMEM_BYTES>>>(x, Wih, Whh, bih, bhh, Wlin, blin, out);
}